// round 13
// baseline (speedup 1.0000x reference)
#include <cuda_runtime.h>
#include <cuda_bf16.h>
#include <cstdint>

// ---------------- problem constants ----------------
#define Rn     20
#define NB     4
#define Hh     480
#define Ww     640
#define hh     120
#define ww     160
#define FC     32
#define DC     32
#define NPIX   (hh*ww)           // 19200
#define NPIXH  (Hh*Ww)           // 307200
#define TOTPX  (Rn*NB*NPIX)      // 1,536,000
#define RB     (Rn*NB)           // 80
#define PADH   (hh+2)            // 122
#define PADW   (ww+2)            // 162
#define PADPIX (PADH*PADW)       // 19764
#define TOTPAD (RB*PADPIX)       // 1,581,120
#define MTILE  256
#define TILES1 78                // ceil(PADPIX/256)
#define STRIP1 582               // 256 + 2*163
#define SPITCH 80                // smem row pitch (bytes)
#define BIAS_I 1282
#define EPSF   1e-6f
#define BETAF  0.01f
#define TPBLKS 38400             // x-transpose blocks (20*480*4)
#define WBLKS  12                // weight-frag blocks
#define POOLB  6000              // pool blocks (TOTPX/256)
#define DTB    2400              // d-transpose blocks (4*120*5)

// ---------------- device scratch ----------------
__device__ __nv_bfloat16 g_xTb[(size_t)NB*Hh*Ww*FC];      // [b][y][x][c] bf16
__device__ uint32_t     g_bfrag1[18*4*32*2];              // conv1 B fragments
__device__ uint32_t     g_bfrag2[18*32*2];                // conv2 B fragments
__device__ float        g_dT[(size_t)NB*NPIX*DC];         // d channel-last fp32
__device__ float        g_rg[TOTPX];
__device__ float        g_cx[TOTPX];
__device__ float        g_cy[TOTPX];
__device__ __nv_bfloat16 g_featp[(size_t)RB*PADPIX*32];   // padded, channel-last
__device__ __nv_bfloat16 g_attdp[(size_t)RB*PADPIX*32];   // padded, channel-last
__device__ float        g_num[Rn];
__device__ float        g_den[Rn];

// ---------------- helpers ----------------
__device__ __forceinline__ uint32_t smem_u32(const void* p) {
    uint32_t a;
    asm("{ .reg .u64 t; cvta.to.shared.u64 t, %1; cvt.u32.u64 %0, t; }"
        : "=r"(a) : "l"(p));
    return a;
}
__device__ __forceinline__ uint32_t pk2(float lo, float hi) {
    uint16_t l = __bfloat16_as_ushort(__float2bfloat16_rn(lo));
    uint16_t h = __bfloat16_as_ushort(__float2bfloat16_rn(hi));
    return (uint32_t)l | ((uint32_t)h << 16);
}
// accumulate 8 bf16 (uint4) * w into 4 float2
__device__ __forceinline__ void corner_acc(const uint4& v, float w, float2 acc[4]) {
    uint32_t u[4] = {v.x, v.y, v.z, v.w};
    #pragma unroll
    for (int i = 0; i < 4; i++) {
        float lo = __uint_as_float(u[i] << 16);
        float hi = __uint_as_float(u[i] & 0xffff0000u);
        acc[i].x = fmaf(w, lo, acc[i].x);
        acc[i].y = fmaf(w, hi, acc[i].y);
    }
}
// 16B cp.async with zero-fill when invalid
__device__ __forceinline__ void cpa16(uint32_t dst, const void* src, bool valid) {
    int sz = valid ? 16 : 0;
    asm volatile("cp.async.cg.shared.global [%0], [%1], 16, %2;"
                 :: "r"(dst), "l"(src), "r"(sz));
}

// ---------------- fused prep: x transpose + weights + pool + d transpose ---
__global__ void __launch_bounds__(256) k_prep(const float* __restrict__ x,
                                              const float* __restrict__ wa,
                                              const float* __restrict__ wp,
                                              const float* __restrict__ dten,
                                              const float* __restrict__ gts,
                                              const float* __restrict__ rnd) {
    int bid = blockIdx.x;
    if (bid < TPBLKS) {
        // x transpose: [b][c][y][x] -> [b][y][x][c] bf16
        __shared__ float tile[32][33];
        int xb = bid % 20; int y = (bid / 20) % Hh; int b = bid / (20 * Hh);
        int x0 = xb * 32;
        int tx = threadIdx.x & 31, ty = threadIdx.x >> 5;
        for (int c = ty; c < 32; c += 8)
            tile[c][tx] = x[(((size_t)b*32 + c)*Hh + y)*Ww + x0 + tx];
        __syncthreads();
        for (int xx = ty; xx < 32; xx += 8)
            g_xTb[(((size_t)b*Hh + y)*Ww + x0 + xx)*32 + tx] =
                __float2bfloat16_rn(tile[tx][xx]);
        return;
    }
    if (bid < TPBLKS + WBLKS) {
        int e = (bid - TPBLKS) * 256 + threadIdx.x;
        if (e < 2304) {             // conv1: 18 kchunks x 4 ntiles x 32 lanes
            int lane = e & 31, nt = (e >> 5) & 3, kchunk = e >> 7;
            int tap = kchunk >> 1, kc = kchunk & 1;
            int ky = tap / 3, kx = tap % 3;
            int n  = nt * 8 + (lane >> 2);
            int ci = kc * 16 + (lane & 3) * 2;
            float w0 = wa[((n*32 + ci    )*3 + ky)*3 + kx];
            float w1 = wa[((n*32 + ci + 1)*3 + ky)*3 + kx];
            float w2 = wa[((n*32 + ci + 8)*3 + ky)*3 + kx];
            float w3 = wa[((n*32 + ci + 9)*3 + ky)*3 + kx];
            g_bfrag1[e*2 + 0] = pk2(w0, w1);
            g_bfrag1[e*2 + 1] = pk2(w2, w3);
        } else if (e < 2880) {      // conv2: 18 kchunks x 32 lanes
            int e2 = e - 2304;
            int lane = e2 & 31, kchunk = e2 >> 5;
            int tap = kchunk >> 1, kc = kchunk & 1;
            int ky = tap / 3, kx = tap % 3;
            int n  = lane >> 2;
            int ci = kc * 16 + (lane & 3) * 2;
            float w0 = 0.f, w1 = 0.f, w2 = 0.f, w3 = 0.f;
            if (n < 4) {
                w0 = wp[((n*32 + ci    )*3 + ky)*3 + kx];
                w1 = wp[((n*32 + ci + 1)*3 + ky)*3 + kx];
                w2 = wp[((n*32 + ci + 8)*3 + ky)*3 + kx];
                w3 = wp[((n*32 + ci + 9)*3 + ky)*3 + kx];
            }
            g_bfrag2[e2*2 + 0] = pk2(w0, w1);
            g_bfrag2[e2*2 + 1] = pk2(w2, w3);
        } else if (e < 2880 + Rn) {
            g_num[e - 2880] = 0.0f;
            g_den[e - 2880] = 0.0f;
        }
        return;
    }
    if (bid < TPBLKS + WBLKS + POOLB) {
        // random pooling + coordinate maps
        int tid = (bid - TPBLKS - WBLKS) * 256 + threadIdx.x;
        int ox = tid % ww; int t2 = tid / ww;
        int oy = t2 % hh;  t2 /= hh;
        int b  = t2 % NB;  int r = t2 / NB;
        const float* rp = rnd + (size_t)(r*NB + b) * NPIXH;
        const float* gp = gts + (size_t)b * NPIXH;
        int gy0 = oy * 4, gx0 = ox * 4;
        float best = -1.0f; int bi = 0, bj = 0;
        #pragma unroll
        for (int i = 0; i < 4; i++) {
            const float4 rv = *(const float4*)(rp + (size_t)(gy0 + i)*Ww + gx0);
            const float4 gv = *(const float4*)(gp + (size_t)(gy0 + i)*Ww + gx0);
            float rr[4] = {rv.x, rv.y, rv.z, rv.w};
            float gg[4] = {gv.x, gv.y, gv.z, gv.w};
            #pragma unroll
            for (int j = 0; j < 4; j++) {
                float m = (gg[j] > 0.1f) ? rr[j] : 0.0f;
                if (m > best) { best = m; bi = i; bj = j; }
            }
        }
        int row = gy0 + bi, col = gx0 + bj;
        float g = gp[(size_t)row*Ww + col];
        g_rg[tid] = (g < 0.1f) ? 0.0f : g;
        int idx = row * Ww + col + BIAS_I;
        int qy = idx / Ww; int qx = idx - qy * Ww;
        g_cx[tid] = ((float)qx / (float)Ww) * (float)(Ww - 1);
        g_cy[tid] = ((float)qy / (float)Hh) * (float)(Hh - 1);
        return;
    }
    {
        // d transpose: [b][c][y][x] -> [b][p][c] fp32
        __shared__ float tile[32][33];
        int bid2 = bid - TPBLKS - WBLKS - POOLB;
        int xb = bid2 % 5; int y = (bid2 / 5) % hh; int b = bid2 / (5 * hh);
        int x0 = xb * 32;
        int tx = threadIdx.x & 31, ty = threadIdx.x >> 5;
        for (int c = ty; c < 32; c += 8)
            tile[c][tx] = dten[(((size_t)b*32 + c)*hh + y)*ww + x0 + tx];
        __syncthreads();
        for (int xx = ty; xx < 32; xx += 8)
            g_dT[(((size_t)b*hh + y)*ww + x0 + xx)*32 + tx] = tile[tx][xx];
        return;
    }
}

// ---------------- bilinear gather: 4 lanes/pixel, b-major block order ------
__global__ void __launch_bounds__(256) k_samplep() {
    int gid = blockIdx.x * 256 + threadIdx.x;
    int pixl = gid >> 2;         // linear slot (b-major order)
    int q    = gid & 3;          // channel quad (8 channels = 16B)
    if (pixl >= TOTPAD) return;
    int p   = pixl % PADPIX;
    int rbl = pixl / PADPIX;     // rbl = b*20 + r
    int b   = rbl / Rn;
    int r   = rbl - b * Rn;
    int rb  = r * NB + b;        // actual rb used by all buffers
    int py = p / PADW, px = p - py * PADW;
    float2 acc[4] = {{0.f,0.f},{0.f,0.f},{0.f,0.f},{0.f,0.f}};
    if (py >= 1 && py <= hh && px >= 1 && px <= ww) {
        int tid = rb * NPIX + (py - 1) * ww + (px - 1);
        float cx = g_cx[tid], cy = g_cy[tid];
        float fx = floorf(cx), fy = floorf(cy);
        int x0 = (int)fx, y0 = (int)fy;
        float wx = cx - fx, wy = cy - fy;
        const uint4* base = (const uint4*)(g_xTb + (size_t)b * Hh * Ww * 32) + q;
        float w00 = (1.f - wx) * (1.f - wy), w10 = wx * (1.f - wy);
        float w01 = (1.f - wx) * wy,         w11 = wx * wy;
        if (y0 <= Hh - 1) {
            corner_acc(base[((size_t)y0*Ww + x0)*4],     w00, acc);
            corner_acc(base[((size_t)y0*Ww + x0 + 1)*4], w10, acc);
        }
        if (y0 + 1 <= Hh - 1) {
            corner_acc(base[((size_t)(y0+1)*Ww + x0)*4],     w01, acc);
            corner_acc(base[((size_t)(y0+1)*Ww + x0 + 1)*4], w11, acc);
        }
    }
    uint4 o;
    o.x = pk2(acc[0].x, acc[0].y);
    o.y = pk2(acc[1].x, acc[1].y);
    o.z = pk2(acc[2].x, acc[2].y);
    o.w = pk2(acc[3].x, acc[3].y);
    size_t pix = (size_t)rb * PADPIX + p;
    *((uint4*)(g_featp + pix*32) + q) = o;
}

// ---------------- conv1: 9-tap bf16 MMA, M=256, 256 thr (R8 config) -------
// warp = 32 flat px (2 m-subtiles); B frags via LDG.64 (L1-resident)
__global__ void __launch_bounds__(256, 4) k_conv1mma(const float* __restrict__ batt) {
    extern __shared__ unsigned char smem[];
    unsigned char* s_strip = smem;                       // STRIP1*SPITCH = 46560
    int rb = blockIdx.y, tile = blockIdx.x;
    int p0 = tile * MTILE, base = p0 - 163;
    int t = threadIdx.x;
    const unsigned char* fp = (const unsigned char*)(g_featp + (size_t)rb * PADPIX * 32);

    // async strip fill (zero-fill OOB)
    uint32_t sbase = smem_u32(s_strip);
    for (int e = t; e < STRIP1*4; e += 256) {
        int r = e >> 2, j = e & 3;
        int gr = base + r;
        bool v = (gr >= 0 && gr < PADPIX);
        cpa16(sbase + r*SPITCH + j*16, fp + (size_t)(v ? gr : 0)*64 + j*16, v);
    }
    asm volatile("cp.async.commit_group;" ::: "memory");
    asm volatile("cp.async.wait_group 0;" ::: "memory");
    __syncthreads();

    int warp = t >> 5, lane = t & 31;
    float acc[2][4][4] = {};
    uint32_t arow = sbase + (warp*32 + (lane & 15))*SPITCH + (lane >> 4)*16;
    const uint2* bfr = (const uint2*)g_bfrag1 + lane;    // per-lane base

    #pragma unroll
    for (int tap = 0; tap < 9; tap++) {
        int tl = (tap/3)*PADW + (tap%3);
        #pragma unroll
        for (int kc = 0; kc < 2; kc++) {
            int kchunk = tap*2 + kc;
            uint2 bb[4];
            #pragma unroll
            for (int nt = 0; nt < 4; nt++)
                bb[nt] = __ldg(bfr + kchunk*128 + nt*32);
            #pragma unroll
            for (int ms = 0; ms < 2; ms++) {
                uint32_t a0,a1,a2,a3;
                uint32_t addr = arow + (ms*16 + tl)*SPITCH + kc*32;
                asm volatile("ldmatrix.sync.aligned.m8n8.x4.shared.b16 {%0,%1,%2,%3}, [%4];"
                    : "=r"(a0),"=r"(a1),"=r"(a2),"=r"(a3) : "r"(addr));
                #pragma unroll
                for (int nt = 0; nt < 4; nt++) {
                    asm volatile("mma.sync.aligned.m16n8k16.row.col.f32.bf16.bf16.f32 "
                        "{%0,%1,%2,%3}, {%4,%5,%6,%7}, {%8,%9}, {%0,%1,%2,%3};"
                        : "+f"(acc[ms][nt][0]),"+f"(acc[ms][nt][1]),
                          "+f"(acc[ms][nt][2]),"+f"(acc[ms][nt][3])
                        : "r"(a0),"r"(a1),"r"(a2),"r"(a3),"r"(bb[nt].x),"r"(bb[nt].y));
                }
            }
        }
    }
    // epilogue: bias -> sigmoid -> * d (channel-last dT) -> attdp; borders 0
    int b = rb & 3;
    int colb = (lane & 3) * 2;
    #pragma unroll
    for (int ms = 0; ms < 2; ms++) {
        #pragma unroll
        for (int rr = 0; rr < 2; rr++) {
            int m = warp*32 + ms*16 + (lane >> 2) + rr*8;
            int p = p0 + m;
            if (p >= PADPIX) continue;
            int py = p / PADW, px = p - py*PADW;
            __nv_bfloat16* op = g_attdp + ((size_t)rb*PADPIX + p)*32;
            if (py >= 1 && py <= hh && px >= 1 && px <= ww) {
                int y = py - 1, x = px - 1;
                const float* dTp = g_dT + ((size_t)b*NPIX + y*ww + x)*32;
                #pragma unroll
                for (int nt = 0; nt < 4; nt++) {
                    int co0 = nt*8 + colb;
                    float v0 = acc[ms][nt][rr*2]     + batt[co0];
                    float v1 = acc[ms][nt][rr*2 + 1] + batt[co0 + 1];
                    float at0 = 1.0f / (1.0f + __expf(-v0));
                    float at1 = 1.0f / (1.0f + __expf(-v1));
                    float2 dv = *(const float2*)(dTp + co0);
                    *reinterpret_cast<uint32_t*>(op + co0) = pk2(at0*dv.x, at1*dv.y);
                }
            } else {
                #pragma unroll
                for (int nt = 0; nt < 4; nt++)
                    *reinterpret_cast<uint32_t*>(op + nt*8 + colb) = 0u;
            }
        }
    }
}

// ---------------- conv2: 9-tap bf16 MMA, M=256, 256 thr + fused loss ------
__global__ void __launch_bounds__(256, 4) k_conv2loss(const float* __restrict__ bpost) {
    extern __shared__ unsigned char smem[];
    unsigned char* s_strip = smem;                       // STRIP1*SPITCH
    int rb = blockIdx.y, tile = blockIdx.x;
    int p0 = tile * MTILE, base = p0 - 163;
    int t = threadIdx.x;
    const unsigned char* ap = (const unsigned char*)(g_attdp + (size_t)rb * PADPIX * 32);

    uint32_t sbase = smem_u32(s_strip);
    for (int e = t; e < STRIP1*4; e += 256) {
        int r = e >> 2, j = e & 3;
        int gr = base + r;
        bool v = (gr >= 0 && gr < PADPIX);
        cpa16(sbase + r*SPITCH + j*16, ap + (size_t)(v ? gr : 0)*64 + j*16, v);
    }
    asm volatile("cp.async.commit_group;" ::: "memory");
    asm volatile("cp.async.wait_group 0;" ::: "memory");
    __syncthreads();

    int warp = t >> 5, lane = t & 31;
    float acc[2][4] = {};
    uint32_t arow = sbase + (warp*32 + (lane & 15))*SPITCH + (lane >> 4)*16;
    const uint2* bfr = (const uint2*)g_bfrag2 + lane;

    #pragma unroll
    for (int tap = 0; tap < 9; tap++) {
        int tl = (tap/3)*PADW + (tap%3);
        #pragma unroll
        for (int kc = 0; kc < 2; kc++) {
            int kchunk = tap*2 + kc;
            uint2 bb = __ldg(bfr + kchunk*32);
            #pragma unroll
            for (int ms = 0; ms < 2; ms++) {
                uint32_t a0,a1,a2,a3;
                uint32_t addr = arow + (ms*16 + tl)*SPITCH + kc*32;
                asm volatile("ldmatrix.sync.aligned.m8n8.x4.shared.b16 {%0,%1,%2,%3}, [%4];"
                    : "=r"(a0),"=r"(a1),"=r"(a2),"=r"(a3) : "r"(addr));
                asm volatile("mma.sync.aligned.m16n8k16.row.col.f32.bf16.bf16.f32 "
                    "{%0,%1,%2,%3}, {%4,%5,%6,%7}, {%8,%9}, {%0,%1,%2,%3};"
                    : "+f"(acc[ms][0]),"+f"(acc[ms][1]),"+f"(acc[ms][2]),"+f"(acc[ms][3])
                    : "r"(a0),"r"(a1),"r"(a2),"r"(a3),"r"(bb.x),"r"(bb.y));
            }
        }
    }

    // fused loss epilogue: ds = acc + bias; smooth-L1 against log-grads of rg
    const int dyk[4] = {0, 1, 1, 1};
    const int dxk[4] = {1, 1, 0, -1};
    float num = 0.0f, den = 0.0f;
    int colb = (lane & 3) * 2;   // co pair; only colb<4 contributes
    const float* rgp = g_rg + (size_t)rb * NPIX;
    if (colb < 4) {
        float bb0 = bpost[colb], bb1 = bpost[colb + 1];
        #pragma unroll
        for (int ms = 0; ms < 2; ms++) {
            #pragma unroll
            for (int rr = 0; rr < 2; rr++) {
                int m = warp*32 + ms*16 + (lane >> 2) + rr*8;
                int p = p0 + m;
                if (p >= PADPIX) continue;
                int py = p / PADW, px = p - py*PADW;
                if (py < 1 || py > hh || px < 1 || px > ww) continue;
                int y = py - 1, x = px - 1;
                float c = rgp[y*ww + x];
                if (c <= 0.1f) continue;
                float logc = __logf(c + EPSF);
                float ds[2] = { acc[ms][rr*2] + bb0, acc[ms][rr*2 + 1] + bb1 };
                #pragma unroll
                for (int cc = 0; cc < 2; cc++) {
                    int k = colb + cc;
                    int yn = y + dyk[k], xn = x + dxk[k];
                    if (yn < hh && xn >= 0 && xn < ww) {
                        float nb = rgp[yn*ww + xn];
                        if (nb > 0.1f) {
                            float grad = logc - __logf(nb + EPSF);
                            float a = fabsf(ds[cc] - grad);
                            float s = (a < BETAF) ? (0.5f/BETAF)*a*a : a - 0.5f*BETAF;
                            num += s; den += 1.0f;
                        }
                    }
                }
            }
        }
    }
    #pragma unroll
    for (int o = 16; o > 0; o >>= 1) {
        num += __shfl_down_sync(0xffffffffu, num, o);
        den += __shfl_down_sync(0xffffffffu, den, o);
    }
    if (lane == 0 && (num != 0.0f || den != 0.0f)) {
        int r = rb >> 2;
        atomicAdd(&g_num[r], num);
        atomicAdd(&g_den[r], den);
    }
}

// ---------------- final: mean of per-r ratios ----------------
__global__ void k_final(float* __restrict__ out) {
    int t = threadIdx.x;
    float v = (t < Rn) ? (g_num[t] / g_den[t]) : 0.0f;
    #pragma unroll
    for (int o = 16; o > 0; o >>= 1) v += __shfl_down_sync(0xffffffffu, v, o);
    if (t == 0) out[0] = v / (float)Rn;
}

// ---------------- launch ----------------
extern "C" void kernel_launch(void* const* d_in, const int* in_sizes, int n_in,
                              void* d_out, int out_size) {
    const float* x     = (const float*)d_in[0];
    const float* dten  = (const float*)d_in[1];
    const float* gts   = (const float*)d_in[2];
    const float* rnd   = (const float*)d_in[3];
    const float* Watt  = (const float*)d_in[4];
    const float* batt  = (const float*)d_in[5];
    const float* Wpost = (const float*)d_in[6];
    const float* bpost = (const float*)d_in[7];
    float* out = (float*)d_out;

    static int attr_done = 0;
    if (!attr_done) {
        cudaFuncSetAttribute(k_conv1mma, cudaFuncAttributeMaxDynamicSharedMemorySize,
                             STRIP1*SPITCH);
        cudaFuncSetAttribute(k_conv2loss, cudaFuncAttributeMaxDynamicSharedMemorySize,
                             STRIP1*SPITCH);
        attr_done = 1;
    }

    k_prep<<<TPBLKS + WBLKS + POOLB + DTB, 256>>>(x, Watt, Wpost, dten, gts, rnd);
    {
        long long tp = (long long)TOTPAD * 4;
        k_samplep<<<(unsigned)((tp + 255)/256), 256>>>();
    }
    k_conv1mma<<<dim3(TILES1, RB), 256, STRIP1*SPITCH>>>(batt);
    k_conv2loss<<<dim3(TILES1, RB), 256, STRIP1*SPITCH>>>(bpost);
    k_final<<<1, 32>>>(out);
}

// round 15
// speedup vs baseline: 1.3251x; 1.3251x over previous
#include <cuda_runtime.h>
#include <cuda_bf16.h>
#include <cstdint>

// ---------------- problem constants ----------------
#define Rn     20
#define NB     4
#define Hh     480
#define Ww     640
#define hh     120
#define ww     160
#define FC     32
#define DC     32
#define NPIX   (hh*ww)           // 19200
#define NPIXH  (Hh*Ww)           // 307200
#define TOTPX  (Rn*NB*NPIX)      // 1,536,000
#define RB     (Rn*NB)           // 80
#define PADH   (hh+2)            // 122
#define PADW   (ww+2)            // 162
#define PADPIX (PADH*PADW)       // 19764
#define TOTPAD (RB*PADPIX)       // 1,581,120
#define MTILE  256
#define TILES1 78                // ceil(PADPIX/256)
#define STRIP1 582               // 256 + 2*163
#define SPITCH 80                // smem row pitch (bytes)
#define BIAS_I 1282
#define EPSF   1e-6f
#define BETAF  0.01f
#define TPBLKS 38400             // transpose blocks (20*480*4)
#define LSENT  -1.0e29f          // masked-sentinel threshold

// ---------------- device scratch ----------------
__device__ __nv_bfloat16 g_xTb[(size_t)NB*Hh*Ww*FC];      // [b][y][x][c] bf16
__device__ uint32_t     g_bfrag1[18*4*32*2];              // conv1 B fragments
__device__ uint32_t     g_bfrag2[18*32*2];                // conv2 B fragments
__device__ float        g_lrg[TOTPX];                     // log(rg+eps) or -1e30
__device__ float        g_cx[TOTPX];
__device__ float        g_cy[TOTPX];
__device__ __nv_bfloat16 g_featp[(size_t)RB*PADPIX*32];   // padded, channel-last
__device__ __nv_bfloat16 g_attdp[(size_t)RB*PADPIX*32];   // padded, channel-last
__device__ float        g_num[Rn];
__device__ float        g_den[Rn];

// ---------------- helpers ----------------
__device__ __forceinline__ uint32_t smem_u32(const void* p) {
    uint32_t a;
    asm("{ .reg .u64 t; cvta.to.shared.u64 t, %1; cvt.u32.u64 %0, t; }"
        : "=r"(a) : "l"(p));
    return a;
}
__device__ __forceinline__ uint32_t pk2(float lo, float hi) {
    uint16_t l = __bfloat16_as_ushort(__float2bfloat16_rn(lo));
    uint16_t h = __bfloat16_as_ushort(__float2bfloat16_rn(hi));
    return (uint32_t)l | ((uint32_t)h << 16);
}
// accumulate 8 bf16 (uint4) * w into 4 float2
__device__ __forceinline__ void corner_acc(const uint4& v, float w, float2 acc[4]) {
    uint32_t u[4] = {v.x, v.y, v.z, v.w};
    #pragma unroll
    for (int i = 0; i < 4; i++) {
        float lo = __uint_as_float(u[i] << 16);
        float hi = __uint_as_float(u[i] & 0xffff0000u);
        acc[i].x = fmaf(w, lo, acc[i].x);
        acc[i].y = fmaf(w, hi, acc[i].y);
    }
}
// 16B cp.async with zero-fill when invalid
__device__ __forceinline__ void cpa16(uint32_t dst, const void* src, bool valid) {
    int sz = valid ? 16 : 0;
    asm volatile("cp.async.cg.shared.global [%0], [%1], 16, %2;"
                 :: "r"(dst), "l"(src), "r"(sz));
}

// ---------------- fused: x transpose + weight fragments + zero accums ------
__global__ void __launch_bounds__(256) k_tp_prep(const float* __restrict__ x,
                                                 const float* __restrict__ wa,
                                                 const float* __restrict__ wp) {
    if (blockIdx.x < TPBLKS) {
        __shared__ float tile[32][33];
        int bid = blockIdx.x;
        int xb = bid % 20; int y = (bid / 20) % Hh; int b = bid / (20 * Hh);
        int x0 = xb * 32;
        int tx = threadIdx.x & 31, ty = threadIdx.x >> 5;
        for (int c = ty; c < 32; c += 8)
            tile[c][tx] = x[(((size_t)b*32 + c)*Hh + y)*Ww + x0 + tx];
        __syncthreads();
        for (int xx = ty; xx < 32; xx += 8)
            g_xTb[(((size_t)b*Hh + y)*Ww + x0 + xx)*32 + tx] =
                __float2bfloat16_rn(tile[tx][xx]);
        return;
    }
    int e = (blockIdx.x - TPBLKS) * 256 + threadIdx.x;
    if (e < 2304) {             // conv1: 18 kchunks x 4 ntiles x 32 lanes
        int lane = e & 31, nt = (e >> 5) & 3, kchunk = e >> 7;
        int tap = kchunk >> 1, kc = kchunk & 1;
        int ky = tap / 3, kx = tap % 3;
        int n  = nt * 8 + (lane >> 2);
        int ci = kc * 16 + (lane & 3) * 2;
        float w0 = wa[((n*32 + ci    )*3 + ky)*3 + kx];
        float w1 = wa[((n*32 + ci + 1)*3 + ky)*3 + kx];
        float w2 = wa[((n*32 + ci + 8)*3 + ky)*3 + kx];
        float w3 = wa[((n*32 + ci + 9)*3 + ky)*3 + kx];
        g_bfrag1[e*2 + 0] = pk2(w0, w1);
        g_bfrag1[e*2 + 1] = pk2(w2, w3);
    } else if (e < 2880) {      // conv2: 18 kchunks x 32 lanes
        int e2 = e - 2304;
        int lane = e2 & 31, kchunk = e2 >> 5;
        int tap = kchunk >> 1, kc = kchunk & 1;
        int ky = tap / 3, kx = tap % 3;
        int n  = lane >> 2;
        int ci = kc * 16 + (lane & 3) * 2;
        float w0 = 0.f, w1 = 0.f, w2 = 0.f, w3 = 0.f;
        if (n < 4) {
            w0 = wp[((n*32 + ci    )*3 + ky)*3 + kx];
            w1 = wp[((n*32 + ci + 1)*3 + ky)*3 + kx];
            w2 = wp[((n*32 + ci + 8)*3 + ky)*3 + kx];
            w3 = wp[((n*32 + ci + 9)*3 + ky)*3 + kx];
        }
        g_bfrag2[e2*2 + 0] = pk2(w0, w1);
        g_bfrag2[e2*2 + 1] = pk2(w2, w3);
    } else if (e < 2880 + Rn) {
        g_num[e - 2880] = 0.0f;
        g_den[e - 2880] = 0.0f;
    }
}

// ---------------- random pooling + coordinate maps + log precompute -------
__global__ void k_pool(const float* __restrict__ gts, const float* __restrict__ rnd) {
    int tid = blockIdx.x * 256 + threadIdx.x;
    if (tid >= TOTPX) return;
    int ox = tid % ww; int t2 = tid / ww;
    int oy = t2 % hh;  t2 /= hh;
    int b  = t2 % NB;  int r = t2 / NB;
    const float* rp = rnd + (size_t)(r*NB + b) * NPIXH;
    const float* gp = gts + (size_t)b * NPIXH;
    int gy0 = oy * 4, gx0 = ox * 4;
    float best = -1.0f; int bi = 0, bj = 0;
    #pragma unroll
    for (int i = 0; i < 4; i++) {
        const float4 rv = *(const float4*)(rp + (size_t)(gy0 + i)*Ww + gx0);
        const float4 gv = *(const float4*)(gp + (size_t)(gy0 + i)*Ww + gx0);
        float rr[4] = {rv.x, rv.y, rv.z, rv.w};
        float gg[4] = {gv.x, gv.y, gv.z, gv.w};
        #pragma unroll
        for (int j = 0; j < 4; j++) {
            float m = (gg[j] > 0.1f) ? rr[j] : 0.0f;
            if (m > best) { best = m; bi = i; bj = j; }
        }
    }
    int row = gy0 + bi, col = gx0 + bj;
    float g = gp[(size_t)row*Ww + col];
    // store log(rg+eps), or sentinel when masked (rg<0.1 -> rg=0 -> masked)
    g_lrg[tid] = (g < 0.1f) ? -1.0e30f : __logf(g + EPSF);
    int idx = row * Ww + col + BIAS_I;
    int qy = idx / Ww; int qx = idx - qy * Ww;
    g_cx[tid] = ((float)qx / (float)Ww) * (float)(Ww - 1);
    g_cy[tid] = ((float)qy / (float)Hh) * (float)(Hh - 1);
}

// ---------------- bilinear gather: 4 lanes/pixel, b-major block order ------
__global__ void __launch_bounds__(256) k_samplep() {
    int gid = blockIdx.x * 256 + threadIdx.x;
    int pixl = gid >> 2;         // linear slot (b-major order)
    int q    = gid & 3;          // channel quad (8 channels = 16B)
    if (pixl >= TOTPAD) return;
    int p   = pixl % PADPIX;
    int rbl = pixl / PADPIX;     // rbl = b*20 + r
    int b   = rbl / Rn;
    int r   = rbl - b * Rn;
    int rb  = r * NB + b;        // actual rb used by all buffers
    int py = p / PADW, px = p - py * PADW;
    float2 acc[4] = {{0.f,0.f},{0.f,0.f},{0.f,0.f},{0.f,0.f}};
    if (py >= 1 && py <= hh && px >= 1 && px <= ww) {
        int tid = rb * NPIX + (py - 1) * ww + (px - 1);
        float cx = g_cx[tid], cy = g_cy[tid];
        float fx = floorf(cx), fy = floorf(cy);
        int x0 = (int)fx, y0 = (int)fy;
        float wx = cx - fx, wy = cy - fy;
        const uint4* base = (const uint4*)(g_xTb + (size_t)b * Hh * Ww * 32) + q;
        float w00 = (1.f - wx) * (1.f - wy), w10 = wx * (1.f - wy);
        float w01 = (1.f - wx) * wy,         w11 = wx * wy;
        if (y0 <= Hh - 1) {
            corner_acc(base[((size_t)y0*Ww + x0)*4],     w00, acc);
            corner_acc(base[((size_t)y0*Ww + x0 + 1)*4], w10, acc);
        }
        if (y0 + 1 <= Hh - 1) {
            corner_acc(base[((size_t)(y0+1)*Ww + x0)*4],     w01, acc);
            corner_acc(base[((size_t)(y0+1)*Ww + x0 + 1)*4], w11, acc);
        }
    }
    uint4 o;
    o.x = pk2(acc[0].x, acc[0].y);
    o.y = pk2(acc[1].x, acc[1].y);
    o.z = pk2(acc[2].x, acc[2].y);
    o.w = pk2(acc[3].x, acc[3].y);
    size_t pix = (size_t)rb * PADPIX + p;
    *((uint4*)(g_featp + pix*32) + q) = o;
}

// ---------------- conv1: 9-tap bf16 MMA, M=256, 256 thr (R8 config) -------
// warp = 32 flat px (2 m-subtiles); B frags via LDG.64 (L1-resident)
__global__ void __launch_bounds__(256, 4) k_conv1mma(const float* __restrict__ dten,
                                                     const float* __restrict__ batt) {
    extern __shared__ unsigned char smem[];
    unsigned char* s_strip = smem;                       // STRIP1*SPITCH = 46560
    int rb = blockIdx.y, tile = blockIdx.x;
    int p0 = tile * MTILE, base = p0 - 163;
    int t = threadIdx.x;
    const unsigned char* fp = (const unsigned char*)(g_featp + (size_t)rb * PADPIX * 32);

    // async strip fill (zero-fill OOB)
    uint32_t sbase = smem_u32(s_strip);
    for (int e = t; e < STRIP1*4; e += 256) {
        int r = e >> 2, j = e & 3;
        int gr = base + r;
        bool v = (gr >= 0 && gr < PADPIX);
        cpa16(sbase + r*SPITCH + j*16, fp + (size_t)(v ? gr : 0)*64 + j*16, v);
    }
    asm volatile("cp.async.commit_group;" ::: "memory");
    asm volatile("cp.async.wait_group 0;" ::: "memory");
    __syncthreads();

    int warp = t >> 5, lane = t & 31;
    float acc[2][4][4] = {};
    uint32_t arow = sbase + (warp*32 + (lane & 15))*SPITCH + (lane >> 4)*16;
    const uint2* bfr = (const uint2*)g_bfrag1 + lane;    // per-lane base

    #pragma unroll
    for (int tap = 0; tap < 9; tap++) {
        int tl = (tap/3)*PADW + (tap%3);
        #pragma unroll
        for (int kc = 0; kc < 2; kc++) {
            int kchunk = tap*2 + kc;
            uint2 bb[4];
            #pragma unroll
            for (int nt = 0; nt < 4; nt++)
                bb[nt] = __ldg(bfr + kchunk*128 + nt*32);
            #pragma unroll
            for (int ms = 0; ms < 2; ms++) {
                uint32_t a0,a1,a2,a3;
                uint32_t addr = arow + (ms*16 + tl)*SPITCH + kc*32;
                asm volatile("ldmatrix.sync.aligned.m8n8.x4.shared.b16 {%0,%1,%2,%3}, [%4];"
                    : "=r"(a0),"=r"(a1),"=r"(a2),"=r"(a3) : "r"(addr));
                #pragma unroll
                for (int nt = 0; nt < 4; nt++) {
                    asm volatile("mma.sync.aligned.m16n8k16.row.col.f32.bf16.bf16.f32 "
                        "{%0,%1,%2,%3}, {%4,%5,%6,%7}, {%8,%9}, {%0,%1,%2,%3};"
                        : "+f"(acc[ms][nt][0]),"+f"(acc[ms][nt][1]),
                          "+f"(acc[ms][nt][2]),"+f"(acc[ms][nt][3])
                        : "r"(a0),"r"(a1),"r"(a2),"r"(a3),"r"(bb[nt].x),"r"(bb[nt].y));
                }
            }
        }
    }
    // epilogue: bias -> sigmoid -> * d -> attdp; borders get zeros
    int b = rb & 3;
    int colb = (lane & 3) * 2;
    #pragma unroll
    for (int ms = 0; ms < 2; ms++) {
        #pragma unroll
        for (int rr = 0; rr < 2; rr++) {
            int m = warp*32 + ms*16 + (lane >> 2) + rr*8;
            int p = p0 + m;
            if (p >= PADPIX) continue;
            int py = p / PADW, px = p - py*PADW;
            __nv_bfloat16* op = g_attdp + ((size_t)rb*PADPIX + p)*32;
            if (py >= 1 && py <= hh && px >= 1 && px <= ww) {
                int y = py - 1, x = px - 1;
                #pragma unroll
                for (int nt = 0; nt < 4; nt++) {
                    int co0 = nt*8 + colb;
                    float v0 = acc[ms][nt][rr*2]     + batt[co0];
                    float v1 = acc[ms][nt][rr*2 + 1] + batt[co0 + 1];
                    float at0 = 1.0f / (1.0f + __expf(-v0));
                    float at1 = 1.0f / (1.0f + __expf(-v1));
                    float d0 = dten[(((size_t)b*DC + co0    )*hh + y)*ww + x];
                    float d1 = dten[(((size_t)b*DC + co0 + 1)*hh + y)*ww + x];
                    *reinterpret_cast<uint32_t*>(op + co0) = pk2(at0*d0, at1*d1);
                }
            } else {
                #pragma unroll
                for (int nt = 0; nt < 4; nt++)
                    *reinterpret_cast<uint32_t*>(op + nt*8 + colb) = 0u;
            }
        }
    }
}

// ---------------- conv2: 9-tap bf16 MMA, M=256, 256 thr + fused loss ------
__global__ void __launch_bounds__(256, 4) k_conv2loss(const float* __restrict__ bpost) {
    extern __shared__ unsigned char smem[];
    unsigned char* s_strip = smem;                       // STRIP1*SPITCH
    int rb = blockIdx.y, tile = blockIdx.x;
    int p0 = tile * MTILE, base = p0 - 163;
    int t = threadIdx.x;
    const unsigned char* ap = (const unsigned char*)(g_attdp + (size_t)rb * PADPIX * 32);

    uint32_t sbase = smem_u32(s_strip);
    for (int e = t; e < STRIP1*4; e += 256) {
        int r = e >> 2, j = e & 3;
        int gr = base + r;
        bool v = (gr >= 0 && gr < PADPIX);
        cpa16(sbase + r*SPITCH + j*16, ap + (size_t)(v ? gr : 0)*64 + j*16, v);
    }
    asm volatile("cp.async.commit_group;" ::: "memory");
    asm volatile("cp.async.wait_group 0;" ::: "memory");
    __syncthreads();

    int warp = t >> 5, lane = t & 31;
    float acc[2][4] = {};
    uint32_t arow = sbase + (warp*32 + (lane & 15))*SPITCH + (lane >> 4)*16;
    const uint2* bfr = (const uint2*)g_bfrag2 + lane;

    #pragma unroll
    for (int tap = 0; tap < 9; tap++) {
        int tl = (tap/3)*PADW + (tap%3);
        #pragma unroll
        for (int kc = 0; kc < 2; kc++) {
            int kchunk = tap*2 + kc;
            uint2 bb = __ldg(bfr + kchunk*32);
            #pragma unroll
            for (int ms = 0; ms < 2; ms++) {
                uint32_t a0,a1,a2,a3;
                uint32_t addr = arow + (ms*16 + tl)*SPITCH + kc*32;
                asm volatile("ldmatrix.sync.aligned.m8n8.x4.shared.b16 {%0,%1,%2,%3}, [%4];"
                    : "=r"(a0),"=r"(a1),"=r"(a2),"=r"(a3) : "r"(addr));
                asm volatile("mma.sync.aligned.m16n8k16.row.col.f32.bf16.bf16.f32 "
                    "{%0,%1,%2,%3}, {%4,%5,%6,%7}, {%8,%9}, {%0,%1,%2,%3};"
                    : "+f"(acc[ms][0]),"+f"(acc[ms][1]),"+f"(acc[ms][2]),"+f"(acc[ms][3])
                    : "r"(a0),"r"(a1),"r"(a2),"r"(a3),"r"(bb.x),"r"(bb.y));
            }
        }
    }

    // fused loss epilogue: ds = acc + bias; smooth-L1 vs precomputed log grads
    const int dyk[4] = {0, 1, 1, 1};
    const int dxk[4] = {1, 1, 0, -1};
    float num = 0.0f, den = 0.0f;
    int colb = (lane & 3) * 2;   // co pair; only colb<4 contributes
    const float* lrgp = g_lrg + (size_t)rb * NPIX;
    if (colb < 4) {
        float bb0 = bpost[colb], bb1 = bpost[colb + 1];
        #pragma unroll
        for (int ms = 0; ms < 2; ms++) {
            #pragma unroll
            for (int rr = 0; rr < 2; rr++) {
                int m = warp*32 + ms*16 + (lane >> 2) + rr*8;
                int p = p0 + m;
                if (p >= PADPIX) continue;
                int py = p / PADW, px = p - py*PADW;
                if (py < 1 || py > hh || px < 1 || px > ww) continue;
                int y = py - 1, x = px - 1;
                float logc = lrgp[y*ww + x];
                if (logc < LSENT) continue;
                float ds[2] = { acc[ms][rr*2] + bb0, acc[ms][rr*2 + 1] + bb1 };
                #pragma unroll
                for (int cc = 0; cc < 2; cc++) {
                    int k = colb + cc;
                    int yn = y + dyk[k], xn = x + dxk[k];
                    if (yn < hh && xn >= 0 && xn < ww) {
                        float lognb = lrgp[yn*ww + xn];
                        if (lognb > LSENT) {
                            float grad = logc - lognb;
                            float a = fabsf(ds[cc] - grad);
                            float s = (a < BETAF) ? (0.5f/BETAF)*a*a : a - 0.5f*BETAF;
                            num += s; den += 1.0f;
                        }
                    }
                }
            }
        }
    }
    #pragma unroll
    for (int o = 16; o > 0; o >>= 1) {
        num += __shfl_down_sync(0xffffffffu, num, o);
        den += __shfl_down_sync(0xffffffffu, den, o);
    }
    if (lane == 0 && (num != 0.0f || den != 0.0f)) {
        int r = rb >> 2;
        atomicAdd(&g_num[r], num);
        atomicAdd(&g_den[r], den);
    }
}

// ---------------- final: mean of per-r ratios ----------------
__global__ void k_final(float* __restrict__ out) {
    int t = threadIdx.x;
    float v = (t < Rn) ? (g_num[t] / g_den[t]) : 0.0f;
    #pragma unroll
    for (int o = 16; o > 0; o >>= 1) v += __shfl_down_sync(0xffffffffu, v, o);
    if (t == 0) out[0] = v / (float)Rn;
}

// ---------------- launch ----------------
extern "C" void kernel_launch(void* const* d_in, const int* in_sizes, int n_in,
                              void* d_out, int out_size) {
    const float* x     = (const float*)d_in[0];
    const float* dten  = (const float*)d_in[1];
    const float* gts   = (const float*)d_in[2];
    const float* rnd   = (const float*)d_in[3];
    const float* Watt  = (const float*)d_in[4];
    const float* batt  = (const float*)d_in[5];
    const float* Wpost = (const float*)d_in[6];
    const float* bpost = (const float*)d_in[7];
    float* out = (float*)d_out;

    static int attr_done = 0;
    if (!attr_done) {
        cudaFuncSetAttribute(k_conv1mma, cudaFuncAttributeMaxDynamicSharedMemorySize,
                             STRIP1*SPITCH);
        cudaFuncSetAttribute(k_conv2loss, cudaFuncAttributeMaxDynamicSharedMemorySize,
                             STRIP1*SPITCH);
        attr_done = 1;
    }

    k_tp_prep<<<TPBLKS + 12, 256>>>(x, Watt, Wpost);
    k_pool<<<TOTPX/256, 256>>>(gts, rnd);
    {
        long long tp = (long long)TOTPAD * 4;
        k_samplep<<<(unsigned)((tp + 255)/256), 256>>>();
    }
    k_conv1mma<<<dim3(TILES1, RB), 256, STRIP1*SPITCH>>>(dten, batt);
    k_conv2loss<<<dim3(TILES1, RB), 256, STRIP1*SPITCH>>>(bpost);
    k_final<<<1, 32>>>(out);
}

// round 16
// speedup vs baseline: 1.3273x; 1.0016x over previous
#include <cuda_runtime.h>
#include <cuda_bf16.h>
#include <cstdint>

// ---------------- problem constants ----------------
#define Rn     20
#define NB     4
#define Hh     480
#define Ww     640
#define hh     120
#define ww     160
#define FC     32
#define DC     32
#define NPIX   (hh*ww)           // 19200
#define NPIXH  (Hh*Ww)           // 307200
#define TOTPX  (Rn*NB*NPIX)      // 1,536,000
#define RB     (Rn*NB)           // 80
#define PADH   (hh+2)            // 122
#define PADW   (ww+2)            // 162
#define PADPIX (PADH*PADW)       // 19764
#define TOTPAD (RB*PADPIX)       // 1,581,120
#define MTILE  256
#define TILES1 78                // ceil(PADPIX/256)
#define STRIP1 582               // 256 + 2*163
#define SPITCH 80                // smem row pitch (bytes)
#define BIAS_I 1282
#define EPSF   1e-6f
#define BETAF  0.01f
#define TPBLKS 38400             // transpose blocks (20*480*4)
#define LSENT  -1.0e29f          // masked-sentinel threshold

// ---------------- device scratch ----------------
__device__ __nv_bfloat16 g_xTb[(size_t)NB*Hh*Ww*FC];      // [b][y][x][c] bf16
__device__ uint32_t     g_bfrag1[18*4*32*2];              // conv1 B fragments
__device__ uint32_t     g_bfrag2[18*32*2];                // conv2 B fragments
__device__ float        g_dT[(size_t)NB*NPIX*DC];         // d channel-last fp32
__device__ float        g_lrg[TOTPX];                     // log(rg+eps) or -1e30
__device__ float        g_cx[TOTPX];
__device__ float        g_cy[TOTPX];
__device__ __nv_bfloat16 g_featp[(size_t)RB*PADPIX*32];   // padded, channel-last
__device__ __nv_bfloat16 g_attdp[(size_t)RB*PADPIX*32];   // padded, channel-last
__device__ float        g_num[Rn];
__device__ float        g_den[Rn];

// ---------------- helpers ----------------
__device__ __forceinline__ uint32_t smem_u32(const void* p) {
    uint32_t a;
    asm("{ .reg .u64 t; cvta.to.shared.u64 t, %1; cvt.u32.u64 %0, t; }"
        : "=r"(a) : "l"(p));
    return a;
}
__device__ __forceinline__ uint32_t pk2(float lo, float hi) {
    uint16_t l = __bfloat16_as_ushort(__float2bfloat16_rn(lo));
    uint16_t h = __bfloat16_as_ushort(__float2bfloat16_rn(hi));
    return (uint32_t)l | ((uint32_t)h << 16);
}
// accumulate 8 bf16 (uint4) * w into 4 float2
__device__ __forceinline__ void corner_acc(const uint4& v, float w, float2 acc[4]) {
    uint32_t u[4] = {v.x, v.y, v.z, v.w};
    #pragma unroll
    for (int i = 0; i < 4; i++) {
        float lo = __uint_as_float(u[i] << 16);
        float hi = __uint_as_float(u[i] & 0xffff0000u);
        acc[i].x = fmaf(w, lo, acc[i].x);
        acc[i].y = fmaf(w, hi, acc[i].y);
    }
}
// 16B cp.async with zero-fill when invalid
__device__ __forceinline__ void cpa16(uint32_t dst, const void* src, bool valid) {
    int sz = valid ? 16 : 0;
    asm volatile("cp.async.cg.shared.global [%0], [%1], 16, %2;"
                 :: "r"(dst), "l"(src), "r"(sz));
}

// ---------------- fused: x transpose + weight fragments + zero accums ------
__global__ void __launch_bounds__(256) k_tp_prep(const float* __restrict__ x,
                                                 const float* __restrict__ wa,
                                                 const float* __restrict__ wp) {
    if (blockIdx.x < TPBLKS) {
        __shared__ float tile[32][33];
        int bid = blockIdx.x;
        int xb = bid % 20; int y = (bid / 20) % Hh; int b = bid / (20 * Hh);
        int x0 = xb * 32;
        int tx = threadIdx.x & 31, ty = threadIdx.x >> 5;
        for (int c = ty; c < 32; c += 8)
            tile[c][tx] = x[(((size_t)b*32 + c)*Hh + y)*Ww + x0 + tx];
        __syncthreads();
        for (int xx = ty; xx < 32; xx += 8)
            g_xTb[(((size_t)b*Hh + y)*Ww + x0 + xx)*32 + tx] =
                __float2bfloat16_rn(tile[tx][xx]);
        return;
    }
    int e = (blockIdx.x - TPBLKS) * 256 + threadIdx.x;
    if (e < 2304) {             // conv1: 18 kchunks x 4 ntiles x 32 lanes
        int lane = e & 31, nt = (e >> 5) & 3, kchunk = e >> 7;
        int tap = kchunk >> 1, kc = kchunk & 1;
        int ky = tap / 3, kx = tap % 3;
        int n  = nt * 8 + (lane >> 2);
        int ci = kc * 16 + (lane & 3) * 2;
        float w0 = wa[((n*32 + ci    )*3 + ky)*3 + kx];
        float w1 = wa[((n*32 + ci + 1)*3 + ky)*3 + kx];
        float w2 = wa[((n*32 + ci + 8)*3 + ky)*3 + kx];
        float w3 = wa[((n*32 + ci + 9)*3 + ky)*3 + kx];
        g_bfrag1[e*2 + 0] = pk2(w0, w1);
        g_bfrag1[e*2 + 1] = pk2(w2, w3);
    } else if (e < 2880) {      // conv2: 18 kchunks x 32 lanes
        int e2 = e - 2304;
        int lane = e2 & 31, kchunk = e2 >> 5;
        int tap = kchunk >> 1, kc = kchunk & 1;
        int ky = tap / 3, kx = tap % 3;
        int n  = lane >> 2;
        int ci = kc * 16 + (lane & 3) * 2;
        float w0 = 0.f, w1 = 0.f, w2 = 0.f, w3 = 0.f;
        if (n < 4) {
            w0 = wp[((n*32 + ci    )*3 + ky)*3 + kx];
            w1 = wp[((n*32 + ci + 1)*3 + ky)*3 + kx];
            w2 = wp[((n*32 + ci + 8)*3 + ky)*3 + kx];
            w3 = wp[((n*32 + ci + 9)*3 + ky)*3 + kx];
        }
        g_bfrag2[e2*2 + 0] = pk2(w0, w1);
        g_bfrag2[e2*2 + 1] = pk2(w2, w3);
    } else if (e < 2880 + Rn) {
        g_num[e - 2880] = 0.0f;
        g_den[e - 2880] = 0.0f;
    }
}

// ---------------- d transpose: [b][c][y][x] -> [b][p][c] fp32 --------------
__global__ void __launch_bounds__(256) k_dT(const float* __restrict__ dten) {
    __shared__ float tile[32][33];
    int bid = blockIdx.x;
    int xb = bid % 5; int y = (bid / 5) % hh; int b = bid / (5 * hh);
    int x0 = xb * 32;
    int tx = threadIdx.x & 31, ty = threadIdx.x >> 5;
    for (int c = ty; c < 32; c += 8)
        tile[c][tx] = dten[(((size_t)b*32 + c)*hh + y)*ww + x0 + tx];
    __syncthreads();
    for (int xx = ty; xx < 32; xx += 8)
        g_dT[(((size_t)b*hh + y)*ww + x0 + xx)*32 + tx] = tile[tx][xx];
}

// ---------------- random pooling + coordinate maps + log precompute -------
__global__ void k_pool(const float* __restrict__ gts, const float* __restrict__ rnd) {
    int tid = blockIdx.x * 256 + threadIdx.x;
    if (tid >= TOTPX) return;
    int ox = tid % ww; int t2 = tid / ww;
    int oy = t2 % hh;  t2 /= hh;
    int b  = t2 % NB;  int r = t2 / NB;
    const float* rp = rnd + (size_t)(r*NB + b) * NPIXH;
    const float* gp = gts + (size_t)b * NPIXH;
    int gy0 = oy * 4, gx0 = ox * 4;
    float best = -1.0f; int bi = 0, bj = 0;
    #pragma unroll
    for (int i = 0; i < 4; i++) {
        const float4 rv = *(const float4*)(rp + (size_t)(gy0 + i)*Ww + gx0);
        const float4 gv = *(const float4*)(gp + (size_t)(gy0 + i)*Ww + gx0);
        float rr[4] = {rv.x, rv.y, rv.z, rv.w};
        float gg[4] = {gv.x, gv.y, gv.z, gv.w};
        #pragma unroll
        for (int j = 0; j < 4; j++) {
            float m = (gg[j] > 0.1f) ? rr[j] : 0.0f;
            if (m > best) { best = m; bi = i; bj = j; }
        }
    }
    int row = gy0 + bi, col = gx0 + bj;
    float g = gp[(size_t)row*Ww + col];
    g_lrg[tid] = (g < 0.1f) ? -1.0e30f : __logf(g + EPSF);
    int idx = row * Ww + col + BIAS_I;
    int qy = idx / Ww; int qx = idx - qy * Ww;
    g_cx[tid] = ((float)qx / (float)Ww) * (float)(Ww - 1);
    g_cy[tid] = ((float)qy / (float)Hh) * (float)(Hh - 1);
}

// ---------------- bilinear gather: 4 lanes/pixel, b-major block order ------
__global__ void __launch_bounds__(256) k_samplep() {
    int gid = blockIdx.x * 256 + threadIdx.x;
    int pixl = gid >> 2;         // linear slot (b-major order)
    int q    = gid & 3;          // channel quad (8 channels = 16B)
    if (pixl >= TOTPAD) return;
    int p   = pixl % PADPIX;
    int rbl = pixl / PADPIX;     // rbl = b*20 + r
    int b   = rbl / Rn;
    int r   = rbl - b * Rn;
    int rb  = r * NB + b;        // actual rb used by all buffers
    int py = p / PADW, px = p - py * PADW;
    float2 acc[4] = {{0.f,0.f},{0.f,0.f},{0.f,0.f},{0.f,0.f}};
    if (py >= 1 && py <= hh && px >= 1 && px <= ww) {
        int tid = rb * NPIX + (py - 1) * ww + (px - 1);
        float cx = g_cx[tid], cy = g_cy[tid];
        float fx = floorf(cx), fy = floorf(cy);
        int x0 = (int)fx, y0 = (int)fy;
        float wx = cx - fx, wy = cy - fy;
        const uint4* base = (const uint4*)(g_xTb + (size_t)b * Hh * Ww * 32) + q;
        float w00 = (1.f - wx) * (1.f - wy), w10 = wx * (1.f - wy);
        float w01 = (1.f - wx) * wy,         w11 = wx * wy;
        if (y0 <= Hh - 1) {
            corner_acc(base[((size_t)y0*Ww + x0)*4],     w00, acc);
            corner_acc(base[((size_t)y0*Ww + x0 + 1)*4], w10, acc);
        }
        if (y0 + 1 <= Hh - 1) {
            corner_acc(base[((size_t)(y0+1)*Ww + x0)*4],     w01, acc);
            corner_acc(base[((size_t)(y0+1)*Ww + x0 + 1)*4], w11, acc);
        }
    }
    uint4 o;
    o.x = pk2(acc[0].x, acc[0].y);
    o.y = pk2(acc[1].x, acc[1].y);
    o.z = pk2(acc[2].x, acc[2].y);
    o.w = pk2(acc[3].x, acc[3].y);
    size_t pix = (size_t)rb * PADPIX + p;
    *((uint4*)(g_featp + pix*32) + q) = o;
}

// ---------------- conv1: 9-tap bf16 MMA, M=256, 256 thr (R8 config) -------
// warp = 32 flat px (2 m-subtiles); B frags via LDG.64 (L1-resident)
__global__ void __launch_bounds__(256, 4) k_conv1mma(const float* __restrict__ batt) {
    extern __shared__ unsigned char smem[];
    unsigned char* s_strip = smem;                       // STRIP1*SPITCH = 46560
    int rb = blockIdx.y, tile = blockIdx.x;
    int p0 = tile * MTILE, base = p0 - 163;
    int t = threadIdx.x;
    const unsigned char* fp = (const unsigned char*)(g_featp + (size_t)rb * PADPIX * 32);

    // async strip fill (zero-fill OOB)
    uint32_t sbase = smem_u32(s_strip);
    for (int e = t; e < STRIP1*4; e += 256) {
        int r = e >> 2, j = e & 3;
        int gr = base + r;
        bool v = (gr >= 0 && gr < PADPIX);
        cpa16(sbase + r*SPITCH + j*16, fp + (size_t)(v ? gr : 0)*64 + j*16, v);
    }
    asm volatile("cp.async.commit_group;" ::: "memory");
    asm volatile("cp.async.wait_group 0;" ::: "memory");
    __syncthreads();

    int warp = t >> 5, lane = t & 31;
    float acc[2][4][4] = {};
    uint32_t arow = sbase + (warp*32 + (lane & 15))*SPITCH + (lane >> 4)*16;
    const uint2* bfr = (const uint2*)g_bfrag1 + lane;    // per-lane base

    #pragma unroll
    for (int tap = 0; tap < 9; tap++) {
        int tl = (tap/3)*PADW + (tap%3);
        #pragma unroll
        for (int kc = 0; kc < 2; kc++) {
            int kchunk = tap*2 + kc;
            uint2 bb[4];
            #pragma unroll
            for (int nt = 0; nt < 4; nt++)
                bb[nt] = __ldg(bfr + kchunk*128 + nt*32);
            #pragma unroll
            for (int ms = 0; ms < 2; ms++) {
                uint32_t a0,a1,a2,a3;
                uint32_t addr = arow + (ms*16 + tl)*SPITCH + kc*32;
                asm volatile("ldmatrix.sync.aligned.m8n8.x4.shared.b16 {%0,%1,%2,%3}, [%4];"
                    : "=r"(a0),"=r"(a1),"=r"(a2),"=r"(a3) : "r"(addr));
                #pragma unroll
                for (int nt = 0; nt < 4; nt++) {
                    asm volatile("mma.sync.aligned.m16n8k16.row.col.f32.bf16.bf16.f32 "
                        "{%0,%1,%2,%3}, {%4,%5,%6,%7}, {%8,%9}, {%0,%1,%2,%3};"
                        : "+f"(acc[ms][nt][0]),"+f"(acc[ms][nt][1]),
                          "+f"(acc[ms][nt][2]),"+f"(acc[ms][nt][3])
                        : "r"(a0),"r"(a1),"r"(a2),"r"(a3),"r"(bb[nt].x),"r"(bb[nt].y));
                }
            }
        }
    }
    // epilogue: bias -> sigmoid -> * d (channel-last dT) -> attdp; borders 0
    int b = rb & 3;
    int colb = (lane & 3) * 2;
    #pragma unroll
    for (int ms = 0; ms < 2; ms++) {
        #pragma unroll
        for (int rr = 0; rr < 2; rr++) {
            int m = warp*32 + ms*16 + (lane >> 2) + rr*8;
            int p = p0 + m;
            if (p >= PADPIX) continue;
            int py = p / PADW, px = p - py*PADW;
            __nv_bfloat16* op = g_attdp + ((size_t)rb*PADPIX + p)*32;
            if (py >= 1 && py <= hh && px >= 1 && px <= ww) {
                int y = py - 1, x = px - 1;
                const float* dTp = g_dT + ((size_t)b*NPIX + y*ww + x)*32;
                #pragma unroll
                for (int nt = 0; nt < 4; nt++) {
                    int co0 = nt*8 + colb;
                    float v0 = acc[ms][nt][rr*2]     + batt[co0];
                    float v1 = acc[ms][nt][rr*2 + 1] + batt[co0 + 1];
                    float at0 = 1.0f / (1.0f + __expf(-v0));
                    float at1 = 1.0f / (1.0f + __expf(-v1));
                    float2 dv = *(const float2*)(dTp + co0);
                    *reinterpret_cast<uint32_t*>(op + co0) = pk2(at0*dv.x, at1*dv.y);
                }
            } else {
                #pragma unroll
                for (int nt = 0; nt < 4; nt++)
                    *reinterpret_cast<uint32_t*>(op + nt*8 + colb) = 0u;
            }
        }
    }
}

// ---------------- conv2: 9-tap bf16 MMA, M=256, 256 thr + fused loss ------
__global__ void __launch_bounds__(256, 4) k_conv2loss(const float* __restrict__ bpost) {
    extern __shared__ unsigned char smem[];
    unsigned char* s_strip = smem;                       // STRIP1*SPITCH
    int rb = blockIdx.y, tile = blockIdx.x;
    int p0 = tile * MTILE, base = p0 - 163;
    int t = threadIdx.x;
    const unsigned char* ap = (const unsigned char*)(g_attdp + (size_t)rb * PADPIX * 32);

    uint32_t sbase = smem_u32(s_strip);
    for (int e = t; e < STRIP1*4; e += 256) {
        int r = e >> 2, j = e & 3;
        int gr = base + r;
        bool v = (gr >= 0 && gr < PADPIX);
        cpa16(sbase + r*SPITCH + j*16, ap + (size_t)(v ? gr : 0)*64 + j*16, v);
    }
    asm volatile("cp.async.commit_group;" ::: "memory");
    asm volatile("cp.async.wait_group 0;" ::: "memory");
    __syncthreads();

    int warp = t >> 5, lane = t & 31;
    float acc[2][4] = {};
    uint32_t arow = sbase + (warp*32 + (lane & 15))*SPITCH + (lane >> 4)*16;
    const uint2* bfr = (const uint2*)g_bfrag2 + lane;

    #pragma unroll
    for (int tap = 0; tap < 9; tap++) {
        int tl = (tap/3)*PADW + (tap%3);
        #pragma unroll
        for (int kc = 0; kc < 2; kc++) {
            int kchunk = tap*2 + kc;
            uint2 bb = __ldg(bfr + kchunk*32);
            #pragma unroll
            for (int ms = 0; ms < 2; ms++) {
                uint32_t a0,a1,a2,a3;
                uint32_t addr = arow + (ms*16 + tl)*SPITCH + kc*32;
                asm volatile("ldmatrix.sync.aligned.m8n8.x4.shared.b16 {%0,%1,%2,%3}, [%4];"
                    : "=r"(a0),"=r"(a1),"=r"(a2),"=r"(a3) : "r"(addr));
                asm volatile("mma.sync.aligned.m16n8k16.row.col.f32.bf16.bf16.f32 "
                    "{%0,%1,%2,%3}, {%4,%5,%6,%7}, {%8,%9}, {%0,%1,%2,%3};"
                    : "+f"(acc[ms][0]),"+f"(acc[ms][1]),"+f"(acc[ms][2]),"+f"(acc[ms][3])
                    : "r"(a0),"r"(a1),"r"(a2),"r"(a3),"r"(bb.x),"r"(bb.y));
            }
        }
    }

    // fused loss epilogue: ds = acc + bias; smooth-L1 vs precomputed log grads
    const int dyk[4] = {0, 1, 1, 1};
    const int dxk[4] = {1, 1, 0, -1};
    float num = 0.0f, den = 0.0f;
    int colb = (lane & 3) * 2;   // co pair; only colb<4 contributes
    const float* lrgp = g_lrg + (size_t)rb * NPIX;
    if (colb < 4) {
        float bb0 = bpost[colb], bb1 = bpost[colb + 1];
        #pragma unroll
        for (int ms = 0; ms < 2; ms++) {
            #pragma unroll
            for (int rr = 0; rr < 2; rr++) {
                int m = warp*32 + ms*16 + (lane >> 2) + rr*8;
                int p = p0 + m;
                if (p >= PADPIX) continue;
                int py = p / PADW, px = p - py*PADW;
                if (py < 1 || py > hh || px < 1 || px > ww) continue;
                int y = py - 1, x = px - 1;
                float logc = lrgp[y*ww + x];
                if (logc < LSENT) continue;
                float ds[2] = { acc[ms][rr*2] + bb0, acc[ms][rr*2 + 1] + bb1 };
                #pragma unroll
                for (int cc = 0; cc < 2; cc++) {
                    int k = colb + cc;
                    int yn = y + dyk[k], xn = x + dxk[k];
                    if (yn < hh && xn >= 0 && xn < ww) {
                        float lognb = lrgp[yn*ww + xn];
                        if (lognb > LSENT) {
                            float grad = logc - lognb;
                            float a = fabsf(ds[cc] - grad);
                            float s = (a < BETAF) ? (0.5f/BETAF)*a*a : a - 0.5f*BETAF;
                            num += s; den += 1.0f;
                        }
                    }
                }
            }
        }
    }
    #pragma unroll
    for (int o = 16; o > 0; o >>= 1) {
        num += __shfl_down_sync(0xffffffffu, num, o);
        den += __shfl_down_sync(0xffffffffu, den, o);
    }
    if (lane == 0 && (num != 0.0f || den != 0.0f)) {
        int r = rb >> 2;
        atomicAdd(&g_num[r], num);
        atomicAdd(&g_den[r], den);
    }
}

// ---------------- final: mean of per-r ratios ----------------
__global__ void k_final(float* __restrict__ out) {
    int t = threadIdx.x;
    float v = (t < Rn) ? (g_num[t] / g_den[t]) : 0.0f;
    #pragma unroll
    for (int o = 16; o > 0; o >>= 1) v += __shfl_down_sync(0xffffffffu, v, o);
    if (t == 0) out[0] = v / (float)Rn;
}

// ---------------- launch ----------------
extern "C" void kernel_launch(void* const* d_in, const int* in_sizes, int n_in,
                              void* d_out, int out_size) {
    const float* x     = (const float*)d_in[0];
    const float* dten  = (const float*)d_in[1];
    const float* gts   = (const float*)d_in[2];
    const float* rnd   = (const float*)d_in[3];
    const float* Watt  = (const float*)d_in[4];
    const float* batt  = (const float*)d_in[5];
    const float* Wpost = (const float*)d_in[6];
    const float* bpost = (const float*)d_in[7];
    float* out = (float*)d_out;

    static int attr_done = 0;
    if (!attr_done) {
        cudaFuncSetAttribute(k_conv1mma, cudaFuncAttributeMaxDynamicSharedMemorySize,
                             STRIP1*SPITCH);
        cudaFuncSetAttribute(k_conv2loss, cudaFuncAttributeMaxDynamicSharedMemorySize,
                             STRIP1*SPITCH);
        attr_done = 1;
    }

    k_tp_prep<<<TPBLKS + 12, 256>>>(x, Watt, Wpost);
    k_dT<<<NB*hh*5, 256>>>(dten);
    k_pool<<<TOTPX/256, 256>>>(gts, rnd);
    {
        long long tp = (long long)TOTPAD * 4;
        k_samplep<<<(unsigned)((tp + 255)/256), 256>>>();
    }
    k_conv1mma<<<dim3(TILES1, RB), 256, STRIP1*SPITCH>>>(batt);
    k_conv2loss<<<dim3(TILES1, RB), 256, STRIP1*SPITCH>>>(bpost);
    k_final<<<1, 32>>>(out);
}